// round 7
// baseline (speedup 1.0000x reference)
#include <cuda_runtime.h>
#include <cuda_bf16.h>
#include <cstdint>

// BilateralFilter (SqueezeSeg): out[b,z,a,k,c] = exp(-||x[b,z,a]-nbr_k||^2 / (2*theta_c^2))
// B=16, Z=64, A=512, K=14 (3x5 minus center), theta=[.015,.015,.01,.01]
// -> per (pixel,k) output float4 = (e1,e1,e2,e2), only 2 distinct exps.
//
// R7: R6 structure (persistent z-march, 1 barrier/z-step, deep prefetch,
// __stcs) with quartered CTAs: TA=128 / 448 thr / 4 CTAs per SM.
// 512 CTAs -> better SM load balance; 3 co-resident CTAs hide each
// CTA's barrier + LDG latency.

#define BB 16
#define ZZ 64
#define AA 512
#define KK 14

#define TA 128                // pixels (a) per CTA
#define NT 448                // threads
#define PT 4                  // outputs per thread per z-step (TA*KK/NT)
#define HW (TA + 4)           // 132 halo width
#define ZC 8                  // z-rows per CTA

__global__ __launch_bounds__(NT, 4)
void bilateral_kernel(const float* __restrict__ x, float4* __restrict__ out)
{
    __shared__ float4 tile[4][HW];   // circular rows, slot = z & 3 ; 8448 B

    const int tid = threadIdx.x;
    const int a0 = blockIdx.x * TA;
    const int z0 = blockIdx.y * ZC;
    const int b  = blockIdx.z;

    // ---- prologue: rows z0-1, z0, z0+1 into their slots ----
    for (int idx = tid; idx < 3 * HW; idx += NT) {
        const int r = idx / HW;
        const int c = idx - r * HW;
        const int gz = z0 + r - 1;
        const int ga = a0 + c - 2;
        float4 v = make_float4(0.f, 0.f, 0.f, 0.f);
        if (gz >= 0 && gz < ZZ && ga >= 0 && ga < AA) {
            const float* p = x + ((size_t)((b * ZZ + gz) * AA + ga)) * 3;
            v.x = p[0]; v.y = p[1]; v.z = p[2];
        }
        tile[gz & 3][c] = v;
    }

    // ---- decode once: k, (i,j) invariant for this thread ----
    const int p0 = tid / KK;          // 0..31
    const int k  = tid - p0 * KK;     // 0..13
    const int kk = k + (k >= 7);      // skip center (flat 7)
    const int i  = kk / 5;            // 0..2
    const int j  = kk - i * 5;        // 0..4

    const float L1 = -1.4426950408889634f / (2.0f * 0.015f * 0.015f);
    const float L2 = -1.4426950408889634f / (2.0f * 0.01f  * 0.01f );

    float4* ob = out + ((size_t)((b * ZZ + z0) * AA + a0)) * KK + tid;

    // ---- initial register prefetch of row z0+2 ----
    const int ga_pf = a0 + tid - 2;
    const bool lane_pf = (tid < HW) && (ga_pf >= 0) && (ga_pf < AA);
    float px = 0.f, py = 0.f, pz = 0.f;
    {
        const int gz = z0 + 2;
        if (lane_pf && gz < ZZ) {
            const float* p = x + ((size_t)((b * ZZ + gz) * AA + ga_pf)) * 3;
            px = p[0]; py = p[1]; pz = p[2];
        }
    }

    #pragma unroll 1
    for (int z = z0; z < z0 + ZC; ++z) {
        __syncthreads();   // orders prior STS before this step's reads,
                           // and prior reads of slot (z+2)&3 before this STS

        // ---- STS prefetched row z+2 (slot disjoint from compute slots) ----
        if (tid < HW && z + 2 <= z0 + ZC)
            tile[(z + 2) & 3][tid] = make_float4(px, py, pz, 0.f);

        // ---- issue LDG prefetch for row z+3 (consumed next step) ----
        px = 0.f; py = 0.f; pz = 0.f;
        {
            const int gz = z + 3;
            if (lane_pf && gz < ZZ && z + 3 <= z0 + ZC) {
                const float* p = x + ((size_t)((b * ZZ + gz) * AA + ga_pf)) * 3;
                px = p[0]; py = p[1]; pz = p[2];
            }
        }

        // ---- compute row z (reads slots (z-1..z+1)&3 only) ----
        const int sc = z & 3;
        const int sn = (z - 1 + i) & 3;
        #pragma unroll
        for (int it = 0; it < PT; ++it) {
            const int p = p0 + it * 32;
            const float4 c4 = tile[sc][p + 2];
            const float4 n4 = tile[sn][p + j];
            const float dx = c4.x - n4.x;
            const float dy = c4.y - n4.y;
            const float dz = c4.z - n4.z;
            const float d2 = fmaf(dz, dz, fmaf(dy, dy, dx * dx));
            const float e1 = exp2f(d2 * L1);
            const float e2 = exp2f(d2 * L2);
            __stcs(&ob[it * NT], make_float4(e1, e1, e2, e2));
        }

        ob += (size_t)AA * KK;
    }
}

extern "C" void kernel_launch(void* const* d_in, const int* in_sizes, int n_in,
                              void* d_out, int out_size)
{
    (void)in_sizes; (void)n_in; (void)out_size;
    const float* x = (const float*)d_in[0];
    float4* out = (float4*)d_out;

    dim3 grid(AA / TA, ZZ / ZC, BB);   // 4 x 8 x 16 = 512 CTAs
    dim3 block(NT);                    // 448 threads
    bilateral_kernel<<<grid, block>>>(x, out);
}

// round 8
// speedup vs baseline: 1.0013x; 1.0013x over previous
#include <cuda_runtime.h>
#include <cuda_bf16.h>
#include <cstdint>

// BilateralFilter (SqueezeSeg): out[b,z,a,k,c] = exp(-||x[b,z,a]-nbr_k||^2 / (2*theta_c^2))
// B=16, Z=64, A=512, K=14 (3x5 minus center), theta=[.015,.015,.01,.01]
// -> per (pixel,k) output float4 = (e1,e1,e2,e2), only 2 distinct exps.
//
// R8: R6 structure (TA=256 / 896 thr / occ 2, persistent z-march, 1 barrier
// per z-step, prefetch depth 2, __stcs) with ZC=4 -> 512 CTAs (1.73 waves):
// work-stealing balances the tail instead of 40 SMs idling half the kernel.
// exp2f -> __expf (guaranteed FMUL+MUFU.EX2).

#define BB 16
#define ZZ 64
#define AA 512
#define KK 14

#define TA 256                // pixels (a) per CTA
#define NT 896                // threads
#define PT 4                  // outputs per thread per z-step
#define HW (TA + 4)           // 260 halo width
#define ZC 4                  // z-rows per CTA

__global__ __launch_bounds__(NT, 2)
void bilateral_kernel(const float* __restrict__ x, float4* __restrict__ out)
{
    __shared__ float4 tile[4][HW];   // circular rows, slot = z & 3

    const int tid = threadIdx.x;
    const int a0 = blockIdx.x * TA;
    const int z0 = blockIdx.y * ZC;
    const int b  = blockIdx.z;

    // ---- prologue: rows z0-1, z0, z0+1 into their slots ----
    for (int idx = tid; idx < 3 * HW; idx += NT) {
        const int r = idx / HW;
        const int c = idx - r * HW;
        const int gz = z0 + r - 1;
        const int ga = a0 + c - 2;
        float4 v = make_float4(0.f, 0.f, 0.f, 0.f);
        if (gz >= 0 && gz < ZZ && ga >= 0 && ga < AA) {
            const float* p = x + ((size_t)((b * ZZ + gz) * AA + ga)) * 3;
            v.x = p[0]; v.y = p[1]; v.z = p[2];
        }
        tile[gz & 3][c] = v;
    }

    // ---- decode once: k, (i,j) invariant for this thread ----
    const int p0 = tid / KK;          // 0..63
    const int k  = tid - p0 * KK;     // 0..13
    const int kk = k + (k >= 7);      // skip center (flat 7)
    const int i  = kk / 5;            // 0..2
    const int j  = kk - i * 5;        // 0..4

    // exp(-d2/(2 th^2)) = __expf(d2 * C), C = -1/(2 th^2)
    const float C1 = -1.0f / (2.0f * 0.015f * 0.015f);
    const float C2 = -1.0f / (2.0f * 0.01f  * 0.01f );

    float4* ob = out + ((size_t)((b * ZZ + z0) * AA + a0)) * KK + tid;

    // ---- initial register prefetch of row z0+2 ----
    const int ga_pf = a0 + tid - 2;
    const bool lane_pf = (tid < HW) && (ga_pf >= 0) && (ga_pf < AA);
    float px = 0.f, py = 0.f, pz = 0.f;
    {
        const int gz = z0 + 2;
        if (lane_pf && gz < ZZ) {
            const float* p = x + ((size_t)((b * ZZ + gz) * AA + ga_pf)) * 3;
            px = p[0]; py = p[1]; pz = p[2];
        }
    }

    #pragma unroll 1
    for (int z = z0; z < z0 + ZC; ++z) {
        __syncthreads();   // orders prior STS before this step's reads,
                           // and prior reads of slot (z+2)&3 before this STS

        // ---- STS prefetched row z+2 (slot disjoint from compute slots) ----
        if (tid < HW && z + 2 <= z0 + ZC)
            tile[(z + 2) & 3][tid] = make_float4(px, py, pz, 0.f);

        // ---- issue LDG prefetch for row z+3 (consumed next step) ----
        px = 0.f; py = 0.f; pz = 0.f;
        {
            const int gz = z + 3;
            if (lane_pf && gz < ZZ && z + 3 <= z0 + ZC) {
                const float* p = x + ((size_t)((b * ZZ + gz) * AA + ga_pf)) * 3;
                px = p[0]; py = p[1]; pz = p[2];
            }
        }

        // ---- compute row z (reads slots (z-1..z+1)&3 only) ----
        const int sc = z & 3;
        const int sn = (z - 1 + i) & 3;
        #pragma unroll
        for (int it = 0; it < PT; ++it) {
            const int p = p0 + it * 64;
            const float4 c4 = tile[sc][p + 2];
            const float4 n4 = tile[sn][p + j];
            const float dx = c4.x - n4.x;
            const float dy = c4.y - n4.y;
            const float dz = c4.z - n4.z;
            const float d2 = fmaf(dz, dz, fmaf(dy, dy, dx * dx));
            const float e1 = __expf(d2 * C1);
            const float e2 = __expf(d2 * C2);
            __stcs(&ob[it * NT], make_float4(e1, e1, e2, e2));
        }

        ob += (size_t)AA * KK;
    }
}

extern "C" void kernel_launch(void* const* d_in, const int* in_sizes, int n_in,
                              void* d_out, int out_size)
{
    (void)in_sizes; (void)n_in; (void)out_size;
    const float* x = (const float*)d_in[0];
    float4* out = (float4*)d_out;

    dim3 grid(AA / TA, ZZ / ZC, BB);   // 2 x 16 x 16 = 512 CTAs
    dim3 block(NT);                    // 896 threads
    bilateral_kernel<<<grid, block>>>(x, out);
}